// round 14
// baseline (speedup 1.0000x reference)
#include <cuda_runtime.h>
#include <cuda_fp16.h>

#define HH 512
#define WW 512
#define BB 8
#define PLANE (HH * WW)
#define TILE_OUT 56     // output columns per warp (64 covered - 8 halo)
#define NTHR 32
#define GY 29
#define SEG 18          // output rows per block (29*18 = 522, tail masked)

__device__ __forceinline__ int refl(int q, int n) {
    if (q < 0) q = -q;
    if (q >= n) q = 2 * n - 2 - q;
    return q;
}

struct Row6 { float g0, g1, g2, p0, p1, p2; };

__device__ __forceinline__ Row6 load6(const float* __restrict__ gb,
                                      const float* __restrict__ pb, int o) {
    Row6 r;
    r.g0 = __ldg(gb + o); r.g1 = __ldg(gb + o + PLANE); r.g2 = __ldg(gb + o + 2 * PLANE);
    r.p0 = __ldg(pb + o); r.p1 = __ldg(pb + o + PLANE); r.p2 = __ldg(pb + o + 2 * PLANE);
    return r;
}

template<bool ADD>
__device__ __forceinline__ void apply6(float vs[21], const Row6& r) {
    const float s = ADD ? 1.f : -1.f;
    const float sg0 = s * r.g0, sg1 = s * r.g1, sg2 = s * r.g2;
    const float sp0 = s * r.p0, sp1 = s * r.p1, sp2 = s * r.p2;
    vs[0] += sg0; vs[1] += sg1; vs[2] += sg2;
    vs[3] += sp0; vs[4] += sp1; vs[5] += sp2;
    vs[6]  = fmaf(sg0, r.g0, vs[6]);  vs[7]  = fmaf(sg0, r.g1, vs[7]);  vs[8]  = fmaf(sg0, r.g2, vs[8]);
    vs[9]  = fmaf(sg1, r.g1, vs[9]);  vs[10] = fmaf(sg1, r.g2, vs[10]); vs[11] = fmaf(sg2, r.g2, vs[11]);
    vs[12] = fmaf(sg0, r.p0, vs[12]); vs[13] = fmaf(sg0, r.p1, vs[13]); vs[14] = fmaf(sg0, r.p2, vs[14]);
    vs[15] = fmaf(sg1, r.p0, vs[15]); vs[16] = fmaf(sg1, r.p1, vs[16]); vs[17] = fmaf(sg1, r.p2, vs[17]);
    vs[18] = fmaf(sg2, r.p0, vs[18]); vs[19] = fmaf(sg2, r.p1, vs[19]); vs[20] = fmaf(sg2, r.p2, vs[20]);
}

// Per-pixel 3x3 symmetric solve: window sums m[21] -> a(9)+b(3) coefficients.
__device__ __forceinline__ void solve3(const float m[21], float ab[12]) {
    const float inv = 1.0f / 25.0f;
    const float eps = 1e-4f;
    const float mI0 = m[0] * inv, mI1 = m[1] * inv, mI2 = m[2] * inv;
    const float mp0 = m[3] * inv, mp1 = m[4] * inv, mp2 = m[5] * inv;

    const float a00 = m[6]  * inv - mI0 * mI0 + eps;
    const float a01 = m[7]  * inv - mI0 * mI1;
    const float a02 = m[8]  * inv - mI0 * mI2;
    const float a11 = m[9]  * inv - mI1 * mI1 + eps;
    const float a12 = m[10] * inv - mI1 * mI2;
    const float a22 = m[11] * inv - mI2 * mI2 + eps;

    const float c00 = m[12] * inv - mI0 * mp0, c01 = m[13] * inv - mI0 * mp1, c02 = m[14] * inv - mI0 * mp2;
    const float c10 = m[15] * inv - mI1 * mp0, c11 = m[16] * inv - mI1 * mp1, c12 = m[17] * inv - mI1 * mp2;
    const float c20 = m[18] * inv - mI2 * mp0, c21 = m[19] * inv - mI2 * mp1, c22 = m[20] * inv - mI2 * mp2;

    float i00 = a11 * a22 - a12 * a12;
    float i01 = a02 * a12 - a01 * a22;
    float i02 = a01 * a12 - a02 * a11;
    float i11 = a00 * a22 - a02 * a02;
    float i12 = a01 * a02 - a00 * a12;
    float i22 = a00 * a11 - a01 * a01;
    const float det = a00 * i00 + a01 * i01 + a02 * i02;
    const float rd = 1.0f / det;
    i00 *= rd; i01 *= rd; i02 *= rd; i11 *= rd; i12 *= rd; i22 *= rd;

    ab[0]  = i00 * c00 + i01 * c10 + i02 * c20;   // A00
    ab[1]  = i00 * c01 + i01 * c11 + i02 * c21;   // A01
    ab[2]  = i00 * c02 + i01 * c12 + i02 * c22;   // A02
    ab[3]  = i01 * c00 + i11 * c10 + i12 * c20;   // A10
    ab[4]  = i01 * c01 + i11 * c11 + i12 * c21;   // A11
    ab[5]  = i01 * c02 + i11 * c12 + i12 * c22;   // A12
    ab[6]  = i02 * c00 + i12 * c10 + i22 * c20;   // A20
    ab[7]  = i02 * c01 + i12 * c11 + i22 * c21;   // A21
    ab[8]  = i02 * c02 + i12 * c12 + i22 * c22;   // A22
    ab[9]  = mp0 - (ab[0] * mI0 + ab[3] * mI1 + ab[6] * mI2);  // b0
    ab[10] = mp1 - (ab[1] * mI0 + ab[4] * mI1 + ab[7] * mI2);  // b1
    ab[11] = mp2 - (ab[2] * mI0 + ab[5] * mI1 + ab[8] * mI2);  // b2
}

__global__ __launch_bounds__(NTHR, 16)
void gf_fused(const float* __restrict__ gd, const float* __restrict__ pd,
              float* __restrict__ out) {
    // 5-row half2-packed ring of h-summed a/b for 2 columns:
    // layout [slot(5)][q(12): col0 pairs 0..5, col1 pairs 6..11][tid]
    __shared__ unsigned ring[5 * 12 * NTHR];

    const unsigned msk = 0xffffffffu;
    const int b = blockIdx.z;
    const int lane = threadIdx.x;
    const int tid = threadIdx.x;
    const int tile = blockIdx.x;                  // 0..9
    const int x0 = tile * TILE_OUT;
    const int c0 = x0 - 4 + 2 * lane;             // this lane's column pair
    const int c1 = c0 + 1;
    const int xr0 = refl(c0, WW);
    const int xr1 = refl(c1, WW);
    const int y0 = blockIdx.y * SEG;
    const int bbase = b * 3 * PLANE;

    const float* gb0 = gd + bbase + xr0;
    const float* gb1 = gd + bbase + xr1;
    const float* pb0 = pd + bbase + xr0;
    const float* pb1 = pd + bbase + xr1;

    float vs0[21], vs1[21];
#pragma unroll
    for (int k = 0; k < 21; k++) { vs0[k] = 0.f; vs1[k] = 0.f; }

    float M0[12], M1[12];
#pragma unroll
    for (int k = 0; k < 12; k++) { M0[k] = 0.f; M1[k] = 0.f; }

#pragma unroll
    for (int i = 0; i < 60; i++) ring[i * NTHR + tid] = 0u;

    const bool v0 = (lane >= 2) && (lane < 30) && (c0 < WW);
    const bool v1 = (lane >= 2) && (lane < 30) && (c1 < WW);
    const float* go0 = gd + bbase + c0;
    const float* go1 = gd + bbase + c1;
    float* ob0 = out + bbase + c0;
    float* ob1 = out + bbase + c1;
    const float inv = 1.0f / 25.0f;

    int slot = 0;
    for (int s = 0; s < SEG + 8; s++) {
        const int yin = y0 - 4 + s;               // row entering vertical window
        const int oadd = refl(yin, HH) * WW;
        Row6 ra0 = load6(gb0, pb0, oadd);
        Row6 ra1 = load6(gb1, pb1, oadd);
        apply6<true>(vs0, ra0);
        apply6<true>(vs1, ra1);

        if (s >= 4) {                             // window = rows yin-4..yin
            // Horizontal 5-tap sums for both columns: 4 SHFL + 5 ADD per k.
            float m0[21], m1[21];
#pragma unroll
            for (int k = 0; k < 21; k++) {
                const float u0 = __shfl_up_sync(msk, vs0[k], 1);
                const float u1 = __shfl_up_sync(msk, vs1[k], 1);
                const float d0 = __shfl_down_sync(msk, vs0[k], 1);
                const float d1 = __shfl_down_sync(msk, vs1[k], 1);
                const float mid = u1 + vs0[k] + vs1[k] + d0;
                m0[k] = mid + u0;
                m1[k] = mid + d1;
            }

            float ab0[12], ab1[12];
            solve3(m0, ab0);
            solve3(m1, ab1);

            // h-sum a/b horizontally (both cols), push into ring, update M.
            unsigned* rs = ring + slot * (12 * NTHR) + tid;
#pragma unroll
            for (int j = 0; j < 6; j++) {
                const int ka = 2 * j, kb = 2 * j + 1;
                const float ua0 = __shfl_up_sync(msk, ab0[ka], 1);
                const float ua1 = __shfl_up_sync(msk, ab1[ka], 1);
                const float da0 = __shfl_down_sync(msk, ab0[ka], 1);
                const float da1 = __shfl_down_sync(msk, ab1[ka], 1);
                const float mida = ua1 + ab0[ka] + ab1[ka] + da0;
                const float h0a = mida + ua0;
                const float h1a = mida + da1;

                const float ub0 = __shfl_up_sync(msk, ab0[kb], 1);
                const float ub1 = __shfl_up_sync(msk, ab1[kb], 1);
                const float db0 = __shfl_down_sync(msk, ab0[kb], 1);
                const float db1 = __shfl_down_sync(msk, ab1[kb], 1);
                const float midb = ub1 + ab0[kb] + ab1[kb] + db0;
                const float h0b = midb + ub0;
                const float h1b = midb + db1;

                // col0
                {
                    unsigned ou = rs[j * NTHR];
                    const float2 o = __half22float2(*reinterpret_cast<__half2*>(&ou));
                    M0[ka] += h0a - o.x;
                    M0[kb] += h0b - o.y;
                    const __half2 nh = __floats2half2_rn(h0a, h0b);
                    rs[j * NTHR] = *reinterpret_cast<const unsigned*>(&nh);
                }
                // col1
                {
                    unsigned ou = rs[(6 + j) * NTHR];
                    const float2 o = __half22float2(*reinterpret_cast<__half2*>(&ou));
                    M1[ka] += h1a - o.x;
                    M1[kb] += h1b - o.y;
                    const __half2 nh = __floats2half2_rn(h1a, h1b);
                    rs[(6 + j) * NTHR] = *reinterpret_cast<const unsigned*>(&nh);
                }
            }

            if (s >= 8) {                         // M = rows yout-2..yout+2
                const int yout = yin - 4;
                if (yout < HH) {
                    const int o = yout * WW;
                    if (v0) {
                        const float g0 = __ldg(go0 + o);
                        const float g1 = __ldg(go0 + o + PLANE);
                        const float g2 = __ldg(go0 + o + 2 * PLANE);
                        ob0[o]             = (g0 * M0[0] + g1 * M0[3] + g2 * M0[6] + M0[9])  * inv;
                        ob0[o + PLANE]     = (g0 * M0[1] + g1 * M0[4] + g2 * M0[7] + M0[10]) * inv;
                        ob0[o + 2 * PLANE] = (g0 * M0[2] + g1 * M0[5] + g2 * M0[8] + M0[11]) * inv;
                    }
                    if (v1) {
                        const float g0 = __ldg(go1 + o);
                        const float g1 = __ldg(go1 + o + PLANE);
                        const float g2 = __ldg(go1 + o + 2 * PLANE);
                        ob1[o]             = (g0 * M1[0] + g1 * M1[3] + g2 * M1[6] + M1[9])  * inv;
                        ob1[o + PLANE]     = (g0 * M1[1] + g1 * M1[4] + g2 * M1[7] + M1[10]) * inv;
                        ob1[o + 2 * PLANE] = (g0 * M1[2] + g1 * M1[5] + g2 * M1[8] + M1[11]) * inv;
                    }
                }
            }

            // Subtract leaving row (L1 hit).
            const int osub = refl(yin - 4, HH) * WW;
            Row6 rs0 = load6(gb0, pb0, osub);
            Row6 rs1 = load6(gb1, pb1, osub);
            apply6<false>(vs0, rs0);
            apply6<false>(vs1, rs1);

            slot++;
            if (slot == 5) slot = 0;
        }
    }
}

extern "C" void kernel_launch(void* const* d_in, const int* in_sizes, int n_in,
                              void* d_out, int out_size) {
    const float* gd = (const float*)d_in[0];
    const float* pd = (const float*)d_in[1];
    float* out = (float*)d_out;

    // Maximize smem carveout so 16 one-warp CTAs (16 x 7.68 KB) fit per SM.
    cudaFuncSetAttribute(gf_fused, cudaFuncAttributePreferredSharedMemoryCarveout, 100);

    dim3 grid(10, GY, BB);   // 10 tiles * 56 cols = 560 >= 512
    dim3 blk(NTHR);
    gf_fused<<<grid, blk>>>(gd, pd, out);
}

// round 16
// speedup vs baseline: 1.0705x; 1.0705x over previous
#include <cuda_runtime.h>
#include <cuda_fp16.h>

#define HH 512
#define WW 512
#define BB 8
#define PLANE (HH * WW)
#define TILE_OUT 56     // output columns per warp (64 covered - 8 halo)
#define NWARP 5
#define NTHR 160
#define GY 27
#define SEG 19          // output rows per block (27*19 = 513, tail masked)

__device__ __forceinline__ int refl(int q, int n) {
    if (q < 0) q = -q;
    if (q >= n) q = 2 * n - 2 - q;
    return q;
}

__device__ __forceinline__ __half2 h2up(__half2 v) {
    unsigned u = *reinterpret_cast<unsigned*>(&v);
    u = __shfl_up_sync(0xffffffffu, u, 1);
    return *reinterpret_cast<__half2*>(&u);
}
__device__ __forceinline__ __half2 h2dn(__half2 v) {
    unsigned u = *reinterpret_cast<unsigned*>(&v);
    u = __shfl_down_sync(0xffffffffu, u, 1);
    return *reinterpret_cast<__half2*>(&u);
}

struct Row6 { float g0, g1, g2, p0, p1, p2; };

__device__ __forceinline__ Row6 load6(const float* __restrict__ gb,
                                      const float* __restrict__ pb, int o) {
    Row6 r;
    r.g0 = __ldg(gb + o); r.g1 = __ldg(gb + o + PLANE); r.g2 = __ldg(gb + o + 2 * PLANE);
    r.p0 = __ldg(pb + o); r.p1 = __ldg(pb + o + PLANE); r.p2 = __ldg(pb + o + 2 * PLANE);
    return r;
}

template<bool ADD>
__device__ __forceinline__ void apply6(float vs[21], const Row6& r) {
    const float s = ADD ? 1.f : -1.f;
    const float sg0 = s * r.g0, sg1 = s * r.g1, sg2 = s * r.g2;
    const float sp0 = s * r.p0, sp1 = s * r.p1, sp2 = s * r.p2;
    vs[0] += sg0; vs[1] += sg1; vs[2] += sg2;
    vs[3] += sp0; vs[4] += sp1; vs[5] += sp2;
    vs[6]  = fmaf(sg0, r.g0, vs[6]);  vs[7]  = fmaf(sg0, r.g1, vs[7]);  vs[8]  = fmaf(sg0, r.g2, vs[8]);
    vs[9]  = fmaf(sg1, r.g1, vs[9]);  vs[10] = fmaf(sg1, r.g2, vs[10]); vs[11] = fmaf(sg2, r.g2, vs[11]);
    vs[12] = fmaf(sg0, r.p0, vs[12]); vs[13] = fmaf(sg0, r.p1, vs[13]); vs[14] = fmaf(sg0, r.p2, vs[14]);
    vs[15] = fmaf(sg1, r.p0, vs[15]); vs[16] = fmaf(sg1, r.p1, vs[16]); vs[17] = fmaf(sg1, r.p2, vs[17]);
    vs[18] = fmaf(sg2, r.p0, vs[18]); vs[19] = fmaf(sg2, r.p1, vs[19]); vs[20] = fmaf(sg2, r.p2, vs[20]);
}

// Per-pixel 3x3 symmetric solve: window sums m[21] -> a(9)+b(3) coefficients.
__device__ __forceinline__ void solve3(const float m[21], float ab[12]) {
    const float inv = 1.0f / 25.0f;
    const float eps = 1e-4f;
    const float mI0 = m[0] * inv, mI1 = m[1] * inv, mI2 = m[2] * inv;
    const float mp0 = m[3] * inv, mp1 = m[4] * inv, mp2 = m[5] * inv;

    const float a00 = m[6]  * inv - mI0 * mI0 + eps;
    const float a01 = m[7]  * inv - mI0 * mI1;
    const float a02 = m[8]  * inv - mI0 * mI2;
    const float a11 = m[9]  * inv - mI1 * mI1 + eps;
    const float a12 = m[10] * inv - mI1 * mI2;
    const float a22 = m[11] * inv - mI2 * mI2 + eps;

    const float c00 = m[12] * inv - mI0 * mp0, c01 = m[13] * inv - mI0 * mp1, c02 = m[14] * inv - mI0 * mp2;
    const float c10 = m[15] * inv - mI1 * mp0, c11 = m[16] * inv - mI1 * mp1, c12 = m[17] * inv - mI1 * mp2;
    const float c20 = m[18] * inv - mI2 * mp0, c21 = m[19] * inv - mI2 * mp1, c22 = m[20] * inv - mI2 * mp2;

    float i00 = a11 * a22 - a12 * a12;
    float i01 = a02 * a12 - a01 * a22;
    float i02 = a01 * a12 - a02 * a11;
    float i11 = a00 * a22 - a02 * a02;
    float i12 = a01 * a02 - a00 * a12;
    float i22 = a00 * a11 - a01 * a01;
    const float det = a00 * i00 + a01 * i01 + a02 * i02;
    const float rd = 1.0f / det;
    i00 *= rd; i01 *= rd; i02 *= rd; i11 *= rd; i12 *= rd; i22 *= rd;

    ab[0]  = i00 * c00 + i01 * c10 + i02 * c20;   // A00
    ab[1]  = i00 * c01 + i01 * c11 + i02 * c21;   // A01
    ab[2]  = i00 * c02 + i01 * c12 + i02 * c22;   // A02
    ab[3]  = i01 * c00 + i11 * c10 + i12 * c20;   // A10
    ab[4]  = i01 * c01 + i11 * c11 + i12 * c21;   // A11
    ab[5]  = i01 * c02 + i11 * c12 + i12 * c22;   // A12
    ab[6]  = i02 * c00 + i12 * c10 + i22 * c20;   // A20
    ab[7]  = i02 * c01 + i12 * c11 + i22 * c21;   // A21
    ab[8]  = i02 * c02 + i12 * c12 + i22 * c22;   // A22
    ab[9]  = mp0 - (ab[0] * mI0 + ab[3] * mI1 + ab[6] * mI2);  // b0
    ab[10] = mp1 - (ab[1] * mI0 + ab[4] * mI1 + ab[7] * mI2);  // b1
    ab[11] = mp2 - (ab[2] * mI0 + ab[5] * mI1 + ab[8] * mI2);  // b2
}

__global__ __launch_bounds__(NTHR, 3)
void gf_fused(const float* __restrict__ gd, const float* __restrict__ pd,
              float* __restrict__ out) {
    // 5-row half2-packed ring of h-summed a/b for 2 columns:
    // layout [slot(5)][q(12): col0 pairs 0..5, col1 pairs 6..11][tid]
    __shared__ unsigned ring[5 * 12 * NTHR];

    const unsigned msk = 0xffffffffu;
    const int b = blockIdx.z;
    const int lane = threadIdx.x & 31;
    const int warp = threadIdx.x >> 5;
    const int tid = threadIdx.x;
    const int tile = blockIdx.x * NWARP + warp;   // 0..9, all in-range
    const int x0 = tile * TILE_OUT;
    const int c0 = x0 - 4 + 2 * lane;             // this lane's column pair
    const int c1 = c0 + 1;
    const int xr0 = refl(c0, WW);
    const int xr1 = refl(c1, WW);
    const int y0 = blockIdx.y * SEG;
    const int bbase = b * 3 * PLANE;

    const float* gb0 = gd + bbase + xr0;
    const float* gb1 = gd + bbase + xr1;
    const float* pb0 = pd + bbase + xr0;
    const float* pb1 = pd + bbase + xr1;

    float vs0[21], vs1[21];
#pragma unroll
    for (int k = 0; k < 21; k++) { vs0[k] = 0.f; vs1[k] = 0.f; }

    float M0[12], M1[12];
#pragma unroll
    for (int k = 0; k < 12; k++) { M0[k] = 0.f; M1[k] = 0.f; }

#pragma unroll
    for (int i = 0; i < 60; i++) ring[i * NTHR + tid] = 0u;

    const bool v0 = (lane >= 2) && (lane < 30) && (c0 < WW);
    const bool v1 = (lane >= 2) && (lane < 30) && (c1 < WW);
    const float* go0 = gd + bbase + c0;
    const float* go1 = gd + bbase + c1;
    float* ob0 = out + bbase + c0;
    float* ob1 = out + bbase + c1;
    const float inv = 1.0f / 25.0f;

    int slot = 0;
    for (int s = 0; s < SEG + 8; s++) {
        const int yin = y0 - 4 + s;               // row entering vertical window
        const int oadd = refl(yin, HH) * WW;
        Row6 ra0 = load6(gb0, pb0, oadd);
        Row6 ra1 = load6(gb1, pb1, oadd);
        apply6<true>(vs0, ra0);
        apply6<true>(vs1, ra1);

        if (s >= 4) {                             // window = rows yin-4..yin
            // Horizontal 5-tap sums for both columns: 4 SHFL + 5 ADD per k.
            float m0[21], m1[21];
#pragma unroll
            for (int k = 0; k < 21; k++) {
                const float u0 = __shfl_up_sync(msk, vs0[k], 1);
                const float u1 = __shfl_up_sync(msk, vs1[k], 1);
                const float d0 = __shfl_down_sync(msk, vs0[k], 1);
                const float d1 = __shfl_down_sync(msk, vs1[k], 1);
                const float mid = u1 + vs0[k] + vs1[k] + d0;
                m0[k] = mid + u0;
                m1[k] = mid + d1;
            }

            float ab0[12], ab1[12];
            solve3(m0, ab0);
            solve3(m1, ab1);

            // h-sum a/b horizontally, half2-packed (2 channels per SHFL);
            // push into ring, update running vertical sums M0/M1.
            unsigned* rs = ring + slot * (12 * NTHR) + tid;
#pragma unroll
            for (int j = 0; j < 6; j++) {
                const int ka = 2 * j, kb = 2 * j + 1;
                const __half2 A0 = __floats2half2_rn(ab0[ka], ab0[kb]);  // col0 pair
                const __half2 A1 = __floats2half2_rn(ab1[ka], ab1[kb]);  // col1 pair
                const __half2 u0 = h2up(A0);
                const __half2 u1 = h2up(A1);
                const __half2 d0 = h2dn(A0);
                const __half2 d1 = h2dn(A1);
                const __half2 mid = __hadd2(__hadd2(u1, A0), __hadd2(A1, d0));
                const __half2 h0 = __hadd2(mid, u0);   // col0 h-sum (2 ch)
                const __half2 h1 = __hadd2(mid, d1);   // col1 h-sum (2 ch)

                // col0
                {
                    unsigned ou = rs[j * NTHR];
                    const float2 o = __half22float2(*reinterpret_cast<__half2*>(&ou));
                    const float2 hn = __half22float2(h0);
                    M0[ka] += hn.x - o.x;
                    M0[kb] += hn.y - o.y;
                    rs[j * NTHR] = *reinterpret_cast<const unsigned*>(&h0);
                }
                // col1
                {
                    unsigned ou = rs[(6 + j) * NTHR];
                    const float2 o = __half22float2(*reinterpret_cast<__half2*>(&ou));
                    const float2 hn = __half22float2(h1);
                    M1[ka] += hn.x - o.x;
                    M1[kb] += hn.y - o.y;
                    rs[(6 + j) * NTHR] = *reinterpret_cast<const unsigned*>(&h1);
                }
            }

            if (s >= 8) {                         // M = rows yout-2..yout+2
                const int yout = yin - 4;
                if (yout < HH) {
                    const int o = yout * WW;
                    if (v0) {
                        const float g0 = __ldg(go0 + o);
                        const float g1 = __ldg(go0 + o + PLANE);
                        const float g2 = __ldg(go0 + o + 2 * PLANE);
                        ob0[o]             = (g0 * M0[0] + g1 * M0[3] + g2 * M0[6] + M0[9])  * inv;
                        ob0[o + PLANE]     = (g0 * M0[1] + g1 * M0[4] + g2 * M0[7] + M0[10]) * inv;
                        ob0[o + 2 * PLANE] = (g0 * M0[2] + g1 * M0[5] + g2 * M0[8] + M0[11]) * inv;
                    }
                    if (v1) {
                        const float g0 = __ldg(go1 + o);
                        const float g1 = __ldg(go1 + o + PLANE);
                        const float g2 = __ldg(go1 + o + 2 * PLANE);
                        ob1[o]             = (g0 * M1[0] + g1 * M1[3] + g2 * M1[6] + M1[9])  * inv;
                        ob1[o + PLANE]     = (g0 * M1[1] + g1 * M1[4] + g2 * M1[7] + M1[10]) * inv;
                        ob1[o + 2 * PLANE] = (g0 * M1[2] + g1 * M1[5] + g2 * M1[8] + M1[11]) * inv;
                    }
                }
            }

            // Subtract leaving row (L1 hit).
            const int osub = refl(yin - 4, HH) * WW;
            Row6 rs0 = load6(gb0, pb0, osub);
            Row6 rs1 = load6(gb1, pb1, osub);
            apply6<false>(vs0, rs0);
            apply6<false>(vs1, rs1);

            slot++;
            if (slot == 5) slot = 0;
        }
    }
}

extern "C" void kernel_launch(void* const* d_in, const int* in_sizes, int n_in,
                              void* d_out, int out_size) {
    const float* gd = (const float*)d_in[0];
    const float* pd = (const float*)d_in[1];
    float* out = (float*)d_out;

    dim3 grid(2, GY, BB);    // 2*5 warps cover 10 tiles * 56 cols = 560 >= 512
    dim3 blk(NTHR);
    gf_fused<<<grid, blk>>>(gd, pd, out);
}

// round 17
// speedup vs baseline: 1.1147x; 1.0413x over previous
#include <cuda_runtime.h>
#include <cuda_fp16.h>

#define HH 512
#define WW 512
#define BB 8
#define PLANE (HH * WW)
#define TILE_OUT 56     // output columns per warp (64 covered - 8 halo)
#define NWARP 5
#define NTHR 160
#define GY 27
#define SEG 19          // output rows per block (27*19 = 513, tail masked)

__device__ __forceinline__ int refl(int q, int n) {
    if (q < 0) q = -q;
    if (q >= n) q = 2 * n - 2 - q;
    return q;
}

__device__ __forceinline__ __half2 h2up(__half2 v) {
    unsigned u = *reinterpret_cast<unsigned*>(&v);
    u = __shfl_up_sync(0xffffffffu, u, 1);
    return *reinterpret_cast<__half2*>(&u);
}
__device__ __forceinline__ __half2 h2dn(__half2 v) {
    unsigned u = *reinterpret_cast<unsigned*>(&v);
    u = __shfl_down_sync(0xffffffffu, u, 1);
    return *reinterpret_cast<__half2*>(&u);
}

struct Row6 { float g0, g1, g2, p0, p1, p2; };

__device__ __forceinline__ Row6 load6(const float* __restrict__ gb,
                                      const float* __restrict__ pb, int o) {
    Row6 r;
    r.g0 = __ldg(gb + o); r.g1 = __ldg(gb + o + PLANE); r.g2 = __ldg(gb + o + 2 * PLANE);
    r.p0 = __ldg(pb + o); r.p1 = __ldg(pb + o + PLANE); r.p2 = __ldg(pb + o + 2 * PLANE);
    return r;
}

template<bool ADD>
__device__ __forceinline__ void apply6(float vs[21], const Row6& r) {
    const float s = ADD ? 1.f : -1.f;
    const float sg0 = s * r.g0, sg1 = s * r.g1, sg2 = s * r.g2;
    const float sp0 = s * r.p0, sp1 = s * r.p1, sp2 = s * r.p2;
    vs[0] += sg0; vs[1] += sg1; vs[2] += sg2;
    vs[3] += sp0; vs[4] += sp1; vs[5] += sp2;
    vs[6]  = fmaf(sg0, r.g0, vs[6]);  vs[7]  = fmaf(sg0, r.g1, vs[7]);  vs[8]  = fmaf(sg0, r.g2, vs[8]);
    vs[9]  = fmaf(sg1, r.g1, vs[9]);  vs[10] = fmaf(sg1, r.g2, vs[10]); vs[11] = fmaf(sg2, r.g2, vs[11]);
    vs[12] = fmaf(sg0, r.p0, vs[12]); vs[13] = fmaf(sg0, r.p1, vs[13]); vs[14] = fmaf(sg0, r.p2, vs[14]);
    vs[15] = fmaf(sg1, r.p0, vs[15]); vs[16] = fmaf(sg1, r.p1, vs[16]); vs[17] = fmaf(sg1, r.p2, vs[17]);
    vs[18] = fmaf(sg2, r.p0, vs[18]); vs[19] = fmaf(sg2, r.p1, vs[19]); vs[20] = fmaf(sg2, r.p2, vs[20]);
}

// Per-pixel 3x3 symmetric solve: window sums m[21] -> a(9)+b(3) coefficients.
__device__ __forceinline__ void solve3(const float m[21], float ab[12]) {
    const float inv = 1.0f / 25.0f;
    const float eps = 1e-4f;
    const float mI0 = m[0] * inv, mI1 = m[1] * inv, mI2 = m[2] * inv;
    const float mp0 = m[3] * inv, mp1 = m[4] * inv, mp2 = m[5] * inv;

    const float a00 = m[6]  * inv - mI0 * mI0 + eps;
    const float a01 = m[7]  * inv - mI0 * mI1;
    const float a02 = m[8]  * inv - mI0 * mI2;
    const float a11 = m[9]  * inv - mI1 * mI1 + eps;
    const float a12 = m[10] * inv - mI1 * mI2;
    const float a22 = m[11] * inv - mI2 * mI2 + eps;

    const float c00 = m[12] * inv - mI0 * mp0, c01 = m[13] * inv - mI0 * mp1, c02 = m[14] * inv - mI0 * mp2;
    const float c10 = m[15] * inv - mI1 * mp0, c11 = m[16] * inv - mI1 * mp1, c12 = m[17] * inv - mI1 * mp2;
    const float c20 = m[18] * inv - mI2 * mp0, c21 = m[19] * inv - mI2 * mp1, c22 = m[20] * inv - mI2 * mp2;

    float i00 = a11 * a22 - a12 * a12;
    float i01 = a02 * a12 - a01 * a22;
    float i02 = a01 * a12 - a02 * a11;
    float i11 = a00 * a22 - a02 * a02;
    float i12 = a01 * a02 - a00 * a12;
    float i22 = a00 * a11 - a01 * a01;
    const float det = a00 * i00 + a01 * i01 + a02 * i02;
    const float rd = 1.0f / det;
    i00 *= rd; i01 *= rd; i02 *= rd; i11 *= rd; i12 *= rd; i22 *= rd;

    ab[0]  = i00 * c00 + i01 * c10 + i02 * c20;   // A00
    ab[1]  = i00 * c01 + i01 * c11 + i02 * c21;   // A01
    ab[2]  = i00 * c02 + i01 * c12 + i02 * c22;   // A02
    ab[3]  = i01 * c00 + i11 * c10 + i12 * c20;   // A10
    ab[4]  = i01 * c01 + i11 * c11 + i12 * c21;   // A11
    ab[5]  = i01 * c02 + i11 * c12 + i12 * c22;   // A12
    ab[6]  = i02 * c00 + i12 * c10 + i22 * c20;   // A20
    ab[7]  = i02 * c01 + i12 * c11 + i22 * c21;   // A21
    ab[8]  = i02 * c02 + i12 * c12 + i22 * c22;   // A22
    ab[9]  = mp0 - (ab[0] * mI0 + ab[3] * mI1 + ab[6] * mI2);  // b0
    ab[10] = mp1 - (ab[1] * mI0 + ab[4] * mI1 + ab[7] * mI2);  // b1
    ab[11] = mp2 - (ab[2] * mI0 + ab[5] * mI1 + ab[8] * mI2);  // b2
}

__global__ __launch_bounds__(NTHR, 3)
void gf_fused(const float* __restrict__ gd, const float* __restrict__ pd,
              float* __restrict__ out) {
    // 5-row ring of h-summed a/b (half2), col0/col1 words paired for 64-bit access:
    // layout [slot(5)][j(6)][tid] of uint2 {col0 pair, col1 pair}
    __shared__ uint2 ring[5 * 6 * NTHR];

    const unsigned msk = 0xffffffffu;
    const int b = blockIdx.z;
    const int lane = threadIdx.x & 31;
    const int warp = threadIdx.x >> 5;
    const int tid = threadIdx.x;
    const int tile = blockIdx.x * NWARP + warp;   // 0..9, all in-range
    const int x0 = tile * TILE_OUT;
    const int c0 = x0 - 4 + 2 * lane;             // this lane's column pair (c0 even)
    const int c1 = c0 + 1;
    const int xr0 = refl(c0, WW);
    const int xr1 = refl(c1, WW);
    const int y0 = blockIdx.y * SEG;
    const int bbase = b * 3 * PLANE;

    const float* gb0 = gd + bbase + xr0;
    const float* gb1 = gd + bbase + xr1;
    const float* pb0 = pd + bbase + xr0;
    const float* pb1 = pd + bbase + xr1;

    float vs0[21], vs1[21];
#pragma unroll
    for (int k = 0; k < 21; k++) { vs0[k] = 0.f; vs1[k] = 0.f; }

    float M0[12], M1[12];
#pragma unroll
    for (int k = 0; k < 12; k++) { M0[k] = 0.f; M1[k] = 0.f; }

#pragma unroll
    for (int i = 0; i < 30; i++) ring[i * NTHR + tid] = make_uint2(0u, 0u);

    // c0 even => c0 < WW implies c1 <= 511, so one validity flag covers both.
    const bool vboth = (lane >= 2) && (lane < 30) && (c0 < WW);
    const float* gout = gd + bbase + c0;          // guidance, float2 at even col
    float* ob = out + bbase + c0;                 // output, float2 at even col
    const float inv = 1.0f / 25.0f;

    int slot = 0;
    for (int s = 0; s < SEG + 8; s++) {
        const int yin = y0 - 4 + s;               // row entering vertical window
        const int oadd = refl(yin, HH) * WW;
        Row6 ra0 = load6(gb0, pb0, oadd);
        Row6 ra1 = load6(gb1, pb1, oadd);
        apply6<true>(vs0, ra0);
        apply6<true>(vs1, ra1);

        if (s >= 4) {                             // window = rows yin-4..yin
            // Horizontal 5-tap sums for both columns: 4 SHFL + 5 ADD per k.
            float m0[21], m1[21];
#pragma unroll
            for (int k = 0; k < 21; k++) {
                const float u0 = __shfl_up_sync(msk, vs0[k], 1);
                const float u1 = __shfl_up_sync(msk, vs1[k], 1);
                const float d0 = __shfl_down_sync(msk, vs0[k], 1);
                const float d1 = __shfl_down_sync(msk, vs1[k], 1);
                const float mid = u1 + vs0[k] + vs1[k] + d0;
                m0[k] = mid + u0;
                m1[k] = mid + d1;
            }

            float ab0[12], ab1[12];
            solve3(m0, ab0);
            solve3(m1, ab1);

            // h-sum a/b horizontally, half2-packed (2 channels per SHFL);
            // push into 64-bit ring words, update running vertical sums M0/M1.
            uint2* rs = ring + slot * (6 * NTHR) + tid;
#pragma unroll
            for (int j = 0; j < 6; j++) {
                const int ka = 2 * j, kb = 2 * j + 1;
                const __half2 A0 = __floats2half2_rn(ab0[ka], ab0[kb]);  // col0 pair
                const __half2 A1 = __floats2half2_rn(ab1[ka], ab1[kb]);  // col1 pair
                const __half2 u0 = h2up(A0);
                const __half2 u1 = h2up(A1);
                const __half2 d0 = h2dn(A0);
                const __half2 d1 = h2dn(A1);
                const __half2 mid = __hadd2(__hadd2(u1, A0), __hadd2(A1, d0));
                const __half2 h0 = __hadd2(mid, u0);   // col0 h-sum (2 ch)
                const __half2 h1 = __hadd2(mid, d1);   // col1 h-sum (2 ch)

                const uint2 ou = rs[j * NTHR];
                const float2 o0 = __half22float2(*reinterpret_cast<const __half2*>(&ou.x));
                const float2 o1 = __half22float2(*reinterpret_cast<const __half2*>(&ou.y));
                const float2 n0 = __half22float2(h0);
                const float2 n1 = __half22float2(h1);
                M0[ka] += n0.x - o0.x;
                M0[kb] += n0.y - o0.y;
                M1[ka] += n1.x - o1.x;
                M1[kb] += n1.y - o1.y;
                rs[j * NTHR] = make_uint2(*reinterpret_cast<const unsigned*>(&h0),
                                          *reinterpret_cast<const unsigned*>(&h1));
            }

            if (s >= 8) {                         // M = rows yout-2..yout+2
                const int yout = yin - 4;
                if (yout < HH && vboth) {
                    const int o = yout * WW;
                    const float2 g0 = *reinterpret_cast<const float2*>(gout + o);
                    const float2 g1 = *reinterpret_cast<const float2*>(gout + o + PLANE);
                    const float2 g2 = *reinterpret_cast<const float2*>(gout + o + 2 * PLANE);
                    float2 r0, r1, r2;
                    r0.x = (g0.x * M0[0] + g1.x * M0[3] + g2.x * M0[6] + M0[9])  * inv;
                    r0.y = (g0.y * M1[0] + g1.y * M1[3] + g2.y * M1[6] + M1[9])  * inv;
                    r1.x = (g0.x * M0[1] + g1.x * M0[4] + g2.x * M0[7] + M0[10]) * inv;
                    r1.y = (g0.y * M1[1] + g1.y * M1[4] + g2.y * M1[7] + M1[10]) * inv;
                    r2.x = (g0.x * M0[2] + g1.x * M0[5] + g2.x * M0[8] + M0[11]) * inv;
                    r2.y = (g0.y * M1[2] + g1.y * M1[5] + g2.y * M1[8] + M1[11]) * inv;
                    *reinterpret_cast<float2*>(ob + o)             = r0;
                    *reinterpret_cast<float2*>(ob + o + PLANE)     = r1;
                    *reinterpret_cast<float2*>(ob + o + 2 * PLANE) = r2;
                }
            }

            // Subtract leaving row (L1 hit).
            const int osub = refl(yin - 4, HH) * WW;
            Row6 rs0 = load6(gb0, pb0, osub);
            Row6 rs1 = load6(gb1, pb1, osub);
            apply6<false>(vs0, rs0);
            apply6<false>(vs1, rs1);

            slot++;
            if (slot == 5) slot = 0;
        }
    }
}

extern "C" void kernel_launch(void* const* d_in, const int* in_sizes, int n_in,
                              void* d_out, int out_size) {
    const float* gd = (const float*)d_in[0];
    const float* pd = (const float*)d_in[1];
    float* out = (float*)d_out;

    dim3 grid(2, GY, BB);    // 2*5 warps cover 10 tiles * 56 cols = 560 >= 512
    dim3 blk(NTHR);
    gf_fused<<<grid, blk>>>(gd, pd, out);
}